// round 1
// baseline (speedup 1.0000x reference)
#include <cuda_runtime.h>
#include <cstdint>

#define NN 100000
#define EE 1600000
#define DD 64

// Scratch (device globals — no allocation allowed)
__device__ float  g_deg[NN];
__device__ float  g_dinv[NN];
__device__ float4 g_agg[NN * (DD / 4)];   // agg[node][16 float4]

// ---------------------------------------------------------------------------
// K1: clear degree
__global__ void clear_deg_kernel() {
    int i = blockIdx.x * blockDim.x + threadIdx.x;
    if (i < NN) g_deg[i] = 0.0f;
}

// K2: in-degree histogram over col (target nodes)
__global__ void deg_kernel(const int* __restrict__ col) {
    int e = blockIdx.x * blockDim.x + threadIdx.x;
    if (e < EE) atomicAdd(&g_deg[col[e]], 1.0f);
}

// K3: dinv = rsqrt(deg+1); agg[i] = x[i] / (deg+1)  (self-loop term, also inits agg)
__global__ void init_kernel(const float4* __restrict__ x4) {
    int idx = blockIdx.x * blockDim.x + threadIdx.x;   // [0, NN*16)
    if (idx >= NN * 16) return;
    int i = idx >> 4;
    float d   = g_deg[i] + 1.0f;
    float inv = 1.0f / d;
    float4 v = x4[idx];
    v.x *= inv; v.y *= inv; v.z *= inv; v.w *= inv;
    g_agg[idx] = v;
    if ((idx & 15) == 0) g_dinv[i] = rsqrtf(d);
}

// K4: edge scatter. 16 threads per edge, one float4 each, vector reduction.
__global__ void scatter_kernel(const int* __restrict__ row,
                               const int* __restrict__ col,
                               const float4* __restrict__ x4) {
    int idx = blockIdx.x * blockDim.x + threadIdx.x;   // [0, EE*16)
    if (idx >= EE * 16) return;
    int e = idx >> 4;
    int j = idx & 15;
    int r = row[e];
    int c = col[e];
    float s = g_dinv[r] * g_dinv[c];
    float4 v = x4[r * 16 + j];
    float vx = v.x * s, vy = v.y * s, vz = v.z * s, vw = v.w * s;
    float4* p = &g_agg[c * 16 + j];
    asm volatile("red.global.add.v4.f32 [%0], {%1,%2,%3,%4};"
                 :: "l"(p), "f"(vx), "f"(vy), "f"(vz), "f"(vw)
                 : "memory");
}

// ---------------------------------------------------------------------------
// K5: out = agg @ W^T + bias.  W is [OUT=64, D=64] row-major.
// Block: 256 threads -> 64 rows x 64 cols tile, 4x4 register micro-tile.
__global__ void gemm_kernel(const float* __restrict__ W,
                            const float* __restrict__ bias,
                            float* __restrict__ out) {
    __shared__ float At[64][68];   // At[k][r]  (A tile transposed), pad 68 keeps 16B align + spreads banks
    __shared__ float Wt[64][68];   // Wt[k][c] = W[c][k]

    int tid  = threadIdx.x;
    int row0 = blockIdx.x * 64;
    const float* A = (const float*)g_agg;

    // load W -> Wt (transposed)
    #pragma unroll
    for (int t = tid; t < 4096; t += 256) {
        int c = t >> 6, k = t & 63;    // t = c*64 + k
        Wt[k][c] = W[t];
    }
    // load A tile -> At (transposed), guard tail block
    #pragma unroll
    for (int t = tid; t < 4096; t += 256) {
        int r = t >> 6, k = t & 63;
        int gr = row0 + r;
        At[k][r] = (gr < NN) ? A[gr * 64 + k] : 0.0f;
    }
    __syncthreads();

    int tx = tid & 15;   // col group
    int ty = tid >> 4;   // row group
    int c0 = tx * 4;
    int r0 = ty * 4;

    float acc[4][4];
    #pragma unroll
    for (int i = 0; i < 4; i++)
        #pragma unroll
        for (int j = 0; j < 4; j++) acc[i][j] = 0.0f;

    #pragma unroll
    for (int k = 0; k < 64; k++) {
        float4 a = *(const float4*)&At[k][r0];
        float4 w = *(const float4*)&Wt[k][c0];
        acc[0][0] += a.x * w.x; acc[0][1] += a.x * w.y; acc[0][2] += a.x * w.z; acc[0][3] += a.x * w.w;
        acc[1][0] += a.y * w.x; acc[1][1] += a.y * w.y; acc[1][2] += a.y * w.z; acc[1][3] += a.y * w.w;
        acc[2][0] += a.z * w.x; acc[2][1] += a.z * w.y; acc[2][2] += a.z * w.z; acc[2][3] += a.z * w.w;
        acc[3][0] += a.w * w.x; acc[3][1] += a.w * w.y; acc[3][2] += a.w * w.z; acc[3][3] += a.w * w.w;
    }

    float4 b4 = *(const float4*)&bias[c0];
    #pragma unroll
    for (int i = 0; i < 4; i++) {
        int gr = row0 + r0 + i;
        if (gr < NN) {
            float4 o;
            o.x = acc[i][0] + b4.x;
            o.y = acc[i][1] + b4.y;
            o.z = acc[i][2] + b4.z;
            o.w = acc[i][3] + b4.w;
            *(float4*)&out[gr * 64 + c0] = o;
        }
    }
}

// ---------------------------------------------------------------------------
extern "C" void kernel_launch(void* const* d_in, const int* in_sizes, int n_in,
                              void* d_out, int out_size) {
    // Identify inputs by element count (robust to metadata ordering).
    const float* x  = nullptr;   // first N*D float tensor is x (x0 is the second, unused)
    const int*   ei = nullptr;   // 2*E int32
    const float* Ww = nullptr;   // OUT*D = 4096
    const float* Wb = nullptr;   // OUT = 64
    for (int i = 0; i < n_in; i++) {
        int sz = in_sizes[i];
        if (sz == 2 * EE)            ei = (const int*)d_in[i];
        else if (sz == DD * DD)      Ww = (const float*)d_in[i];
        else if (sz == DD)           Wb = (const float*)d_in[i];
        else if (sz == NN * DD && !x) x = (const float*)d_in[i];
    }
    const int*    row = ei;        // edge_index[0] = source
    const int*    col = ei + EE;   // edge_index[1] = target
    const float4* x4  = (const float4*)x;
    float*        out = (float*)d_out;

    clear_deg_kernel<<<(NN + 255) / 256, 256>>>();
    deg_kernel<<<(EE + 255) / 256, 256>>>(col);
    init_kernel<<<(NN * 16 + 255) / 256, 256>>>(x4);
    scatter_kernel<<<(EE * 16 + 255) / 256, 256>>>(row, col, x4);
    gemm_kernel<<<(NN + 63) / 64, 256>>>(Ww, Wb, out);
}

// round 2
// speedup vs baseline: 1.3216x; 1.3216x over previous
#include <cuda_runtime.h>
#include <cstdint>

#define NN 100000
#define EE 1600000
#define DD 64
#define NB 98          // ceil(NN/1024)

// ---------------- device scratch (no allocation allowed) -------------------
__device__ int    g_degi[NN];      // in-degree histogram
__device__ int    g_cur[NN];       // binning cursors
__device__ int    g_off[NN];       // exclusive scan within 1024-block
__device__ int    g_start[NN];     // global CSR start
__device__ int    g_bsum[128];     // per-block sums
__device__ int    g_bpre[128];     // exclusive scan of block sums
__device__ float  g_dinv[NN];      // rsqrt(deg+1)
__device__ float  g_invdeg[NN];    // 1/(deg+1)
__device__ int    g_csr[EE];       // source node per CSR slot
__device__ float4 g_y[NN * 16];    // y = x @ W^T   [N,64]

// ---------------------------------------------------------------------------
__global__ void clear_kernel() {
    int i = blockIdx.x * blockDim.x + threadIdx.x;
    if (i < NN) { g_degi[i] = 0; g_cur[i] = 0; }
}

__global__ void deg_kernel(const int* __restrict__ col) {
    int e = blockIdx.x * blockDim.x + threadIdx.x;
    if (e < EE) atomicAdd(&g_degi[col[e]], 1);
}

// scan step 1: per-1024-block exclusive scan + block sum
__global__ void scan1_kernel() {
    __shared__ int s[1024];
    int tid = threadIdx.x;
    int i = blockIdx.x * 1024 + tid;
    int v = (i < NN) ? g_degi[i] : 0;
    s[tid] = v;
    __syncthreads();
    #pragma unroll
    for (int d = 1; d < 1024; d <<= 1) {
        int t = (tid >= d) ? s[tid - d] : 0;
        __syncthreads();
        s[tid] += t;
        __syncthreads();
    }
    if (i < NN) g_off[i] = s[tid] - v;            // exclusive
    if (tid == 1023) g_bsum[blockIdx.x] = s[1023];
}

// scan step 2: single-block exclusive scan of NB block sums
__global__ void scan2_kernel() {
    __shared__ int s[128];
    int tid = threadIdx.x;
    int v = (tid < NB) ? g_bsum[tid] : 0;
    s[tid] = v;
    __syncthreads();
    #pragma unroll
    for (int d = 1; d < 128; d <<= 1) {
        int t = (tid >= d) ? s[tid - d] : 0;
        __syncthreads();
        s[tid] += t;
        __syncthreads();
    }
    if (tid < NB) g_bpre[tid] = s[tid] - v;       // exclusive
}

// finalize: global CSR starts + normalization factors
__global__ void finalize_kernel() {
    int i = blockIdx.x * blockDim.x + threadIdx.x;
    if (i >= NN) return;
    g_start[i] = g_off[i] + g_bpre[i >> 10];
    float d = (float)g_degi[i] + 1.0f;            // + self loop
    g_dinv[i]   = rsqrtf(d);
    g_invdeg[i] = 1.0f / d;
}

// bin edges into CSR by target node
__global__ void bin_kernel(const int* __restrict__ row,
                           const int* __restrict__ col) {
    int e = blockIdx.x * blockDim.x + threadIdx.x;
    if (e >= EE) return;
    int c = col[e];
    int pos = g_start[c] + atomicAdd(&g_cur[c], 1);
    g_csr[pos] = row[e];
}

// ---------------------------------------------------------------------------
// y = x @ W^T  (no bias; bias fused into gather). W is [64,64] row-major.
__global__ void gemm_kernel(const float* __restrict__ W,
                            const float* __restrict__ x) {
    __shared__ float At[64][68];
    __shared__ float Wt[64][68];

    int tid  = threadIdx.x;
    int row0 = blockIdx.x * 64;
    float* Y = (float*)g_y;

    #pragma unroll
    for (int t = tid; t < 4096; t += 256) {
        int c = t >> 6, k = t & 63;
        Wt[k][c] = W[t];
    }
    #pragma unroll
    for (int t = tid; t < 4096; t += 256) {
        int r = t >> 6, k = t & 63;
        int gr = row0 + r;
        At[k][r] = (gr < NN) ? x[gr * 64 + k] : 0.0f;
    }
    __syncthreads();

    int tx = tid & 15, ty = tid >> 4;
    int c0 = tx * 4, r0 = ty * 4;

    float acc[4][4];
    #pragma unroll
    for (int i = 0; i < 4; i++)
        #pragma unroll
        for (int j = 0; j < 4; j++) acc[i][j] = 0.0f;

    #pragma unroll
    for (int k = 0; k < 64; k++) {
        float4 a = *(const float4*)&At[k][r0];
        float4 w = *(const float4*)&Wt[k][c0];
        acc[0][0] += a.x * w.x; acc[0][1] += a.x * w.y; acc[0][2] += a.x * w.z; acc[0][3] += a.x * w.w;
        acc[1][0] += a.y * w.x; acc[1][1] += a.y * w.y; acc[1][2] += a.y * w.z; acc[1][3] += a.y * w.w;
        acc[2][0] += a.z * w.x; acc[2][1] += a.z * w.y; acc[2][2] += a.z * w.z; acc[2][3] += a.z * w.w;
        acc[3][0] += a.w * w.x; acc[3][1] += a.w * w.y; acc[3][2] += a.w * w.z; acc[3][3] += a.w * w.w;
    }

    #pragma unroll
    for (int i = 0; i < 4; i++) {
        int gr = row0 + r0 + i;
        if (gr < NN) {
            float4 o = { acc[i][0], acc[i][1], acc[i][2], acc[i][3] };
            *(float4*)&Y[gr * 64 + c0] = o;
        }
    }
}

// ---------------------------------------------------------------------------
// gather: out[c] = dinv[c] * sum_r dinv[r]*y[r]  +  y[c]/deg[c]  +  bias
// 16 threads per target node; thread j owns float4 column j. 2x unrolled.
__global__ void gather_kernel(const float* __restrict__ bias,
                              float4* __restrict__ out4) {
    int t = blockIdx.x * blockDim.x + threadIdx.x;
    int c = t >> 4;
    if (c >= NN) return;
    int j = t & 15;

    int start = g_start[c];
    int cnt   = g_degi[c];

    float4 acc = make_float4(0.f, 0.f, 0.f, 0.f);
    int k = 0;
    for (; k + 2 <= cnt; k += 2) {
        int r0 = g_csr[start + k];
        int r1 = g_csr[start + k + 1];
        float w0 = g_dinv[r0];
        float w1 = g_dinv[r1];
        float4 v0 = g_y[r0 * 16 + j];
        float4 v1 = g_y[r1 * 16 + j];
        acc.x += w0 * v0.x + w1 * v1.x;
        acc.y += w0 * v0.y + w1 * v1.y;
        acc.z += w0 * v0.z + w1 * v1.z;
        acc.w += w0 * v0.w + w1 * v1.w;
    }
    if (k < cnt) {
        int r0 = g_csr[start + k];
        float w0 = g_dinv[r0];
        float4 v0 = g_y[r0 * 16 + j];
        acc.x += w0 * v0.x;
        acc.y += w0 * v0.y;
        acc.z += w0 * v0.z;
        acc.w += w0 * v0.w;
    }

    float dc  = g_dinv[c];
    float inv = g_invdeg[c];
    float4 self = g_y[c * 16 + j];
    float4 b4 = ((const float4*)bias)[j];

    float4 o;
    o.x = dc * acc.x + inv * self.x + b4.x;
    o.y = dc * acc.y + inv * self.y + b4.y;
    o.z = dc * acc.z + inv * self.z + b4.z;
    o.w = dc * acc.w + inv * self.w + b4.w;
    out4[c * 16 + j] = o;
}

// ---------------------------------------------------------------------------
extern "C" void kernel_launch(void* const* d_in, const int* in_sizes, int n_in,
                              void* d_out, int out_size) {
    const float* x  = nullptr;
    const int*   ei = nullptr;
    const float* Ww = nullptr;
    const float* Wb = nullptr;
    for (int i = 0; i < n_in; i++) {
        int sz = in_sizes[i];
        if (sz == 2 * EE)             ei = (const int*)d_in[i];
        else if (sz == DD * DD)       Ww = (const float*)d_in[i];
        else if (sz == DD)            Wb = (const float*)d_in[i];
        else if (sz == NN * DD && !x) x  = (const float*)d_in[i];
    }
    const int* row = ei;          // sources
    const int* col = ei + EE;     // targets
    float4* out4 = (float4*)d_out;

    clear_kernel   <<<(NN + 255) / 256, 256>>>();
    deg_kernel     <<<(EE + 255) / 256, 256>>>(col);
    scan1_kernel   <<<NB, 1024>>>();
    scan2_kernel   <<<1, 128>>>();
    finalize_kernel<<<(NN + 255) / 256, 256>>>();
    bin_kernel     <<<(EE + 255) / 256, 256>>>(row, col);
    gemm_kernel    <<<(NN + 63) / 64, 256>>>(Ww, x);
    gather_kernel  <<<(NN * 16 + 255) / 256, 256>>>(Wb, out4);
}

// round 3
// speedup vs baseline: 1.5678x; 1.1863x over previous
#include <cuda_runtime.h>
#include <cstdint>

#define NN 100000
#define EE 1600000
#define DD 64
#define NB 98            // ceil(NN/1024)
#define GEMM_BLOCKS 782  // ceil(NN/128)
#define DEG_BLOCKS 6250  // EE/256

// ---------------- device scratch ----------------
__device__ int    g_degi[NN];
__device__ int    g_cur[NN];
__device__ int    g_start[NN];
__device__ float  g_dinv[NN];
__device__ float  g_invdeg[NN];
__device__ int    g_csr[EE];
__device__ float4 g_y[NN * 16];                 // y = x @ W^T
__device__ unsigned long long g_state[NB];      // lookback: flag<<32 | value
__device__ int    g_ticket;

// ---------------------------------------------------------------------------
__global__ void clear_kernel() {
    int i = blockIdx.x * blockDim.x + threadIdx.x;
    if (i < NN) { g_degi[i] = 0; g_cur[i] = 0; }
    if (i < NB) g_state[i] = 0ULL;
    if (i == 0) g_ticket = 0;
}

// ---------------------------------------------------------------------------
__device__ __forceinline__ unsigned f2tf32(float f) {
    unsigned u;
    asm("cvt.rna.tf32.f32 %0, %1;" : "=r"(u) : "f"(f));
    return u;
}

__device__ __forceinline__ void mma_tf32(float acc[4], unsigned a0, unsigned a1,
                                         unsigned a2, unsigned a3,
                                         unsigned b0, unsigned b1) {
    asm volatile(
        "mma.sync.aligned.m16n8k8.row.col.f32.tf32.tf32.f32 "
        "{%0,%1,%2,%3}, {%4,%5,%6,%7}, {%8,%9}, {%0,%1,%2,%3};"
        : "+f"(acc[0]), "+f"(acc[1]), "+f"(acc[2]), "+f"(acc[3])
        : "r"(a0), "r"(a1), "r"(a2), "r"(a3), "r"(b0), "r"(b1));
}

// Fused: blocks [0,GEMM_BLOCKS) compute y = x @ W^T (tf32 MMA);
//        blocks [GEMM_BLOCKS, +DEG_BLOCKS) build the in-degree histogram.
__global__ __launch_bounds__(256) void fused_gemm_deg_kernel(
        const float* __restrict__ W, const float* __restrict__ x,
        const int* __restrict__ col) {
    __shared__ unsigned sW[64 * 68];   // tf32 W, pitch 68 => conflict-free b-frag LDS
    int tid = threadIdx.x;

    if (blockIdx.x >= GEMM_BLOCKS) {
        int e = (blockIdx.x - GEMM_BLOCKS) * 256 + tid;
        if (e < EE) atomicAdd(&g_degi[col[e]], 1);
        return;
    }

    // stage + convert W: sW[n*68 + k] = tf32(W[n][k])
    #pragma unroll
    for (int t = tid; t < 4096; t += 256) {
        int n = t >> 6, k = t & 63;
        sW[n * 68 + k] = f2tf32(W[t]);
    }
    __syncthreads();

    int warp = tid >> 5, lane = tid & 31;
    int gid = lane >> 2, tg = lane & 3;
    int r0 = blockIdx.x * 128 + warp * 16;
    int rA = r0 + gid;
    int rB = rA + 8;
    int rAc = rA < NN ? rA : NN - 1;
    int rBc = rB < NN ? rB : NN - 1;
    const float* pA = x + rAc * 64 + tg;
    const float* pB = x + rBc * 64 + tg;

    float acc[8][4];
    #pragma unroll
    for (int n = 0; n < 8; n++)
        #pragma unroll
        for (int j = 0; j < 4; j++) acc[n][j] = 0.0f;

    #pragma unroll
    for (int s = 0; s < 8; s++) {
        int k0 = s * 8;
        unsigned a0 = f2tf32(pA[k0]);
        unsigned a1 = f2tf32(pB[k0]);
        unsigned a2 = f2tf32(pA[k0 + 4]);
        unsigned a3 = f2tf32(pB[k0 + 4]);
        #pragma unroll
        for (int n = 0; n < 8; n++) {
            unsigned b0 = sW[(n * 8 + gid) * 68 + k0 + tg];
            unsigned b1 = sW[(n * 8 + gid) * 68 + k0 + tg + 4];
            mma_tf32(acc[n], a0, a1, a2, a3, b0, b1);
        }
    }

    float2* Y2 = (float2*)g_y;
    #pragma unroll
    for (int n = 0; n < 8; n++) {
        int cidx = n * 4 + tg;      // float2 column index (cols n*8+2tg, +1)
        if (rA < NN) Y2[rA * 32 + cidx] = make_float2(acc[n][0], acc[n][1]);
        if (rB < NN) Y2[rB * 32 + cidx] = make_float2(acc[n][2], acc[n][3]);
    }
}

// ---------------------------------------------------------------------------
// Single-pass scan (decoupled lookback) + finalize dinv/invdeg.
__global__ void scan_kernel() {
    __shared__ int wsum[32];
    __shared__ int sh_tile;
    __shared__ int sh_prefix;
    int tid = threadIdx.x, lane = tid & 31, wid = tid >> 5;

    if (tid == 0) sh_tile = atomicAdd(&g_ticket, 1);
    __syncthreads();
    int tile = sh_tile;
    int i = tile * 1024 + tid;
    int v = (i < NN) ? g_degi[i] : 0;

    // intra-warp inclusive scan
    int xs = v;
    #pragma unroll
    for (int d = 1; d < 32; d <<= 1) {
        int t = __shfl_up_sync(0xffffffffu, xs, d);
        if (lane >= d) xs += t;
    }
    if (lane == 31) wsum[wid] = xs;
    __syncthreads();
    if (wid == 0) {
        int s = wsum[lane];
        #pragma unroll
        for (int d = 1; d < 32; d <<= 1) {
            int t = __shfl_up_sync(0xffffffffu, s, d);
            if (lane >= d) s += t;
        }
        wsum[lane] = s;
    }
    __syncthreads();
    int incl = xs + (wid ? wsum[wid - 1] : 0);
    int total = wsum[31];

    if (tid == 0) {
        unsigned long long pack =
            ((unsigned long long)(tile == 0 ? 2u : 1u) << 32) | (unsigned)total;
        atomicExch(&g_state[tile], pack);
    }

    if (wid == 0) {
        int prefix = 0;
        if (tile > 0) {
            int base = tile - 1;
            while (true) {
                int t = base - lane;
                unsigned long long s;
                if (t >= 0) {
                    do { s = atomicAdd(&g_state[t], 0ULL); } while ((unsigned)(s >> 32) == 0u);
                } else {
                    s = (2ULL << 32);
                }
                unsigned flag = (unsigned)(s >> 32);
                int val = (int)(unsigned)s;
                unsigned ball = __ballot_sync(0xffffffffu, flag == 2u);
                int firstInc = __ffs(ball) - 1;     // closest INC going back
                int contrib = ball ? ((lane <= firstInc) ? val : 0) : val;
                #pragma unroll
                for (int d = 16; d; d >>= 1)
                    contrib += __shfl_xor_sync(0xffffffffu, contrib, d);
                prefix += contrib;
                if (ball) break;
                base -= 32;
            }
            if (lane == 0)
                atomicExch(&g_state[tile],
                           (2ULL << 32) | (unsigned)(prefix + total));
        }
        if (lane == 0) sh_prefix = prefix;
    }
    __syncthreads();
    int prefix = sh_prefix;
    if (i < NN) {
        g_start[i] = prefix + incl - v;   // exclusive
        float df = (float)v + 1.0f;       // + self loop
        g_dinv[i]   = rsqrtf(df);
        g_invdeg[i] = 1.0f / df;
    }
}

// ---------------------------------------------------------------------------
__global__ void bin_kernel(const int* __restrict__ row,
                           const int* __restrict__ col) {
    int e = blockIdx.x * blockDim.x + threadIdx.x;
    if (e >= EE) return;
    int c = col[e];
    int pos = g_start[c] + atomicAdd(&g_cur[c], 1);
    g_csr[pos] = row[e];
}

// ---------------------------------------------------------------------------
// gather: out[c] = dinv[c] * sum_r dinv[r]*y[r] + y[c]/deg[c] + bias
__global__ void gather_kernel(const float* __restrict__ bias,
                              float4* __restrict__ out4) {
    int t = blockIdx.x * blockDim.x + threadIdx.x;
    int c = t >> 4;
    if (c >= NN) return;
    int j = t & 15;

    int start = g_start[c];
    int cnt   = g_degi[c];

    float4 acc = make_float4(0.f, 0.f, 0.f, 0.f);
    int k = 0;
    for (; k + 4 <= cnt; k += 4) {
        int r0 = g_csr[start + k];
        int r1 = g_csr[start + k + 1];
        int r2 = g_csr[start + k + 2];
        int r3 = g_csr[start + k + 3];
        float w0 = g_dinv[r0], w1 = g_dinv[r1], w2 = g_dinv[r2], w3 = g_dinv[r3];
        float4 v0 = g_y[r0 * 16 + j];
        float4 v1 = g_y[r1 * 16 + j];
        float4 v2 = g_y[r2 * 16 + j];
        float4 v3 = g_y[r3 * 16 + j];
        acc.x += w0 * v0.x + w1 * v1.x + w2 * v2.x + w3 * v3.x;
        acc.y += w0 * v0.y + w1 * v1.y + w2 * v2.y + w3 * v3.y;
        acc.z += w0 * v0.z + w1 * v1.z + w2 * v2.z + w3 * v3.z;
        acc.w += w0 * v0.w + w1 * v1.w + w2 * v2.w + w3 * v3.w;
    }
    for (; k < cnt; k++) {
        int r0 = g_csr[start + k];
        float w0 = g_dinv[r0];
        float4 v0 = g_y[r0 * 16 + j];
        acc.x += w0 * v0.x;
        acc.y += w0 * v0.y;
        acc.z += w0 * v0.z;
        acc.w += w0 * v0.w;
    }

    float dc  = g_dinv[c];
    float inv = g_invdeg[c];
    float4 self = g_y[c * 16 + j];
    float4 b4 = ((const float4*)bias)[j];

    float4 o;
    o.x = dc * acc.x + inv * self.x + b4.x;
    o.y = dc * acc.y + inv * self.y + b4.y;
    o.z = dc * acc.z + inv * self.z + b4.z;
    o.w = dc * acc.w + inv * self.w + b4.w;
    out4[c * 16 + j] = o;
}

// ---------------------------------------------------------------------------
extern "C" void kernel_launch(void* const* d_in, const int* in_sizes, int n_in,
                              void* d_out, int out_size) {
    const float* x  = nullptr;
    const int*   ei = nullptr;
    const float* Ww = nullptr;
    const float* Wb = nullptr;
    for (int i = 0; i < n_in; i++) {
        int sz = in_sizes[i];
        if (sz == 2 * EE)             ei = (const int*)d_in[i];
        else if (sz == DD * DD)       Ww = (const float*)d_in[i];
        else if (sz == DD)            Wb = (const float*)d_in[i];
        else if (sz == NN * DD && !x) x  = (const float*)d_in[i];
    }
    const int* row = ei;          // sources
    const int* col = ei + EE;     // targets
    float4* out4 = (float4*)d_out;

    clear_kernel        <<<(NN + 255) / 256, 256>>>();
    fused_gemm_deg_kernel<<<GEMM_BLOCKS + DEG_BLOCKS, 256>>>(Ww, x, col);
    scan_kernel         <<<NB, 1024>>>();
    bin_kernel          <<<(EE + 255) / 256, 256>>>(row, col);
    gather_kernel       <<<(NN * 16 + 255) / 256, 256>>>(Wb, out4);
}